// round 4
// baseline (speedup 1.0000x reference)
#include <cuda_runtime.h>
#include <cuda_bf16.h>

#define BINS 10
#define TPB  256
#define GRID (148 * 8)

// __device__ globals are zero-initialized at module load; the LAST block of
// every launch resets them after finalizing, so every launch (and every graph
// replay) starts clean. No allocs, single launch node.
__device__ double             g_loss_sum[BINS];
__device__ unsigned long long g_count[BINS];
__device__ unsigned int       g_ticket;

__global__ __launch_bounds__(TPB, 8)
void ghm_fused_kernel(const float4* __restrict__ x4,
                      const float4* __restrict__ t4,
                      const float*  __restrict__ x1,
                      const float*  __restrict__ t1,
                      int n4, int n, long long N,
                      float* __restrict__ out)
{
    // acc[b*TPB + tid] : (.x = log2-domain loss sum, .y = count). Bank index is
    // tid-determined regardless of bin -> conflict-free by construction.
    __shared__ float2 acc[BINS * TPB];

    const int tid = threadIdx.x;
#pragma unroll
    for (int k = 0; k < BINS; k++)
        acc[k * TPB + tid] = make_float2(0.0f, 0.0f);
    __syncthreads();

    const int stride = gridDim.x * blockDim.x;
    for (int i = blockIdx.x * blockDim.x + tid; i < n4; i += stride) {
        float4 xv = __ldcs(&x4[i]);            // streaming: evict-first
        float4 tv = __ldcs(&t4[i]);
        float xs[4] = {xv.x, xv.y, xv.z, xv.w};
        float ts[4] = {tv.x, tv.y, tv.z, tv.w};
#pragma unroll
        for (int j = 0; j < 4; j++) {
            float xx = xs[j], tt = ts[j];
            float g  = fabsf(xx - tt);
            int   b  = (int)(g * 9.9999f);      // g < 1 strictly -> b in [0,9]
            float l1 = __log2f(xx);
            float l2 = __log2f(1.0f - xx);
            float loss2 = fmaf(tt, l1 - l2, l2); // scaled by -ln2 at finalize
            int addr = b * TPB + tid;
            float2 a = acc[addr];
            a.x += loss2;
            a.y += 1.0f;
            acc[addr] = a;
        }
    }

    // scalar tail (n % 4): block 0 only
    if (blockIdx.x == 0) {
        for (int k = n4 * 4 + tid; k < n; k += blockDim.x) {
            float xx = x1[k], tt = t1[k];
            float g  = fabsf(xx - tt);
            int   b  = (int)(g * 9.9999f);
            float l1 = __log2f(xx);
            float l2 = __log2f(1.0f - xx);
            float loss2 = fmaf(tt, l1 - l2, l2);
            int addr = b * TPB + tid;
            float2 a = acc[addr];
            a.x += loss2;
            a.y += 1.0f;
            acc[addr] = a;
        }
    }
    __syncthreads();

    // block tree reduction over tid for all bins
    for (int s = TPB / 2; s > 0; s >>= 1) {
        if (tid < s) {
#pragma unroll
            for (int k = 0; k < BINS; k++) {
                float2 a = acc[k * TPB + tid];
                float2 b = acc[k * TPB + tid + s];
                a.x += b.x; a.y += b.y;
                acc[k * TPB + tid] = a;
            }
        }
        __syncthreads();
    }

    if (tid < BINS) {
        float2 a = acc[tid * TPB];
        atomicAdd(&g_loss_sum[tid], (double)a.x);
        atomicAdd(&g_count[tid], (unsigned long long)(a.y + 0.5f));
    }

    // last-block finalize + reset (fused epilogue)
    __shared__ unsigned int s_is_last;
    if (tid == 0) {
        __threadfence();
        unsigned int prev = atomicAdd(&g_ticket, 1u);
        s_is_last = (prev == (unsigned int)gridDim.x - 1u) ? 1u : 0u;
    }
    __syncthreads();

    if (s_is_last && tid == 0) {
        __threadfence();                     // all blocks' atomics visible
        const double NEG_LN2 = -0.6931471805599453;
        float nonempty = 0.0f;
#pragma unroll
        for (int k = 0; k < BINS; k++)
            nonempty += (g_count[k] > 0ull) ? 1.0f : 0.0f;

        const float Nf = (float)N;
        double total = 0.0;
#pragma unroll
        for (int k = 0; k < BINS; k++) {
            float cntf = (float)g_count[k];              // match jnp f32 cast
            float gd   = fmaxf(cntf * nonempty, 1.0f);
            float beta = Nf / gd;
            total += (double)beta * (NEG_LN2 * g_loss_sum[k]);
        }
        out[0] = (float)(total / (double)N);

        // reset for the next launch / graph replay
#pragma unroll
        for (int k = 0; k < BINS; k++) {
            g_loss_sum[k] = 0.0;
            g_count[k]    = 0ull;
        }
        __threadfence();
        g_ticket = 0u;
    }
}

extern "C" void kernel_launch(void* const* d_in, const int* in_sizes, int n_in,
                              void* d_out, int out_size)
{
    const float* x = (const float*)d_in[0];
    const float* t = (const float*)d_in[1];
    float* out = (float*)d_out;

    const int n  = in_sizes[0];
    const int n4 = n >> 2;

    int blocks = GRID;
    int needed = (n4 + TPB - 1) / TPB;
    if (needed < 1) needed = 1;
    if (blocks > needed) blocks = needed;

    ghm_fused_kernel<<<blocks, TPB>>>(
        (const float4*)x, (const float4*)t, x, t, n4, n, (long long)n, out);
}

// round 6
// speedup vs baseline: 1.3346x; 1.3346x over previous
#include <cuda_runtime.h>
#include <cuda_bf16.h>

#define BINS 10
#define TPB  256
#define GRID (148 * 6)

// __device__ globals are zero-initialized at module load; the LAST block of
// every launch resets them after finalizing, so every launch (and every graph
// replay) starts clean. No allocs, single launch node.
__device__ double             g_loss_sum[BINS];
__device__ unsigned long long g_count[BINS];
__device__ unsigned int       g_ticket;

__device__ __forceinline__ void ghm_accum(float2* acc, int tid, float4 xv, float4 tv)
{
    float xs[4] = {xv.x, xv.y, xv.z, xv.w};
    float ts[4] = {tv.x, tv.y, tv.z, tv.w};
#pragma unroll
    for (int j = 0; j < 4; j++) {
        float xx = xs[j], tt = ts[j];
        float g  = fabsf(xx - tt);
        int   b  = (int)(g * 9.9999f);          // g < 1 strictly -> b in [0,9]
        float l1 = __log2f(xx);
        float l2 = __log2f(1.0f - xx);
        float loss2 = fmaf(tt, l1 - l2, l2);    // scaled by -ln2 at finalize
        int addr = b * TPB + tid;
        float2 a = acc[addr];
        a.x += loss2;
        a.y += 1.0f;
        acc[addr] = a;
    }
}

__global__ __launch_bounds__(TPB, 6)
void ghm_fused_kernel(const float4* __restrict__ x4,
                      const float4* __restrict__ t4,
                      const float*  __restrict__ x1,
                      const float*  __restrict__ t1,
                      int n4, int n, long long N,
                      float* __restrict__ out)
{
    // acc[b*TPB + tid] : (.x = log2-domain loss sum, .y = count). Bank index is
    // tid-determined regardless of bin -> conflict-free by construction.
    __shared__ float2 acc[BINS * TPB];

    const int tid = threadIdx.x;
#pragma unroll
    for (int k = 0; k < BINS; k++)
        acc[k * TPB + tid] = make_float2(0.0f, 0.0f);
    __syncthreads();

    const int stride = gridDim.x * blockDim.x;
    int i = blockIdx.x * blockDim.x + tid;

    // 2-stage software pipeline: next iteration's loads issue before the
    // current iteration's compute + smem-RAW chain.
    if (i < n4) {
        float4 xv = x4[i];
        float4 tv = t4[i];
        for (; i + stride < n4; i += stride) {
            float4 xn = x4[i + stride];
            float4 tn = t4[i + stride];
            ghm_accum(acc, tid, xv, tv);
            xv = xn; tv = tn;
        }
        ghm_accum(acc, tid, xv, tv);
    }

    // scalar tail (n % 4): block 0 only
    if (blockIdx.x == 0) {
        for (int k = n4 * 4 + tid; k < n; k += blockDim.x) {
            float xx = x1[k], tt = t1[k];
            float g  = fabsf(xx - tt);
            int   b  = (int)(g * 9.9999f);
            float l1 = __log2f(xx);
            float l2 = __log2f(1.0f - xx);
            float loss2 = fmaf(tt, l1 - l2, l2);
            int addr = b * TPB + tid;
            float2 a = acc[addr];
            a.x += loss2;
            a.y += 1.0f;
            acc[addr] = a;
        }
    }
    __syncthreads();

    // block tree reduction over tid for all bins
    for (int s = TPB / 2; s > 0; s >>= 1) {
        if (tid < s) {
#pragma unroll
            for (int k = 0; k < BINS; k++) {
                float2 a = acc[k * TPB + tid];
                float2 b = acc[k * TPB + tid + s];
                a.x += b.x; a.y += b.y;
                acc[k * TPB + tid] = a;
            }
        }
        __syncthreads();
    }

    if (tid < BINS) {
        float2 a = acc[tid * TPB];
        atomicAdd(&g_loss_sum[tid], (double)a.x);
        atomicAdd(&g_count[tid], (unsigned long long)(a.y + 0.5f));
    }

    // last-block finalize + reset (fused epilogue)
    __shared__ unsigned int s_is_last;
    if (tid == 0) {
        __threadfence();
        unsigned int prev = atomicAdd(&g_ticket, 1u);
        s_is_last = (prev == (unsigned int)gridDim.x - 1u) ? 1u : 0u;
    }
    __syncthreads();

    if (s_is_last && tid == 0) {
        __threadfence();                     // all blocks' atomics visible
        const double NEG_LN2 = -0.6931471805599453;
        float nonempty = 0.0f;
#pragma unroll
        for (int k = 0; k < BINS; k++)
            nonempty += (g_count[k] > 0ull) ? 1.0f : 0.0f;

        const float Nf = (float)N;
        double total = 0.0;
#pragma unroll
        for (int k = 0; k < BINS; k++) {
            float cntf = (float)g_count[k];              // match jnp f32 cast
            float gd   = fmaxf(cntf * nonempty, 1.0f);
            float beta = Nf / gd;
            total += (double)beta * (NEG_LN2 * g_loss_sum[k]);
        }
        out[0] = (float)(total / (double)N);

        // reset for the next launch / graph replay
#pragma unroll
        for (int k = 0; k < BINS; k++) {
            g_loss_sum[k] = 0.0;
            g_count[k]    = 0ull;
        }
        __threadfence();
        g_ticket = 0u;
    }
}

extern "C" void kernel_launch(void* const* d_in, const int* in_sizes, int n_in,
                              void* d_out, int out_size)
{
    const float* x = (const float*)d_in[0];
    const float* t = (const float*)d_in[1];
    float* out = (float*)d_out;

    const int n  = in_sizes[0];
    const int n4 = n >> 2;

    int blocks = GRID;
    int needed = (n4 + TPB - 1) / TPB;
    if (needed < 1) needed = 1;
    if (blocks > needed) blocks = needed;

    ghm_fused_kernel<<<blocks, TPB>>>(
        (const float4*)x, (const float4*)t, x, t, n4, n, (long long)n, out);
}